// round 4
// baseline (speedup 1.0000x reference)
#include <cuda_runtime.h>
#include <math.h>

#define BB    4
#define NSEQ  8192
#define DM    512
#define MTOT  (BB * NSEQ)        // 32768
#define SPLITK 16
#define KC    (NSEQ / SPLITK)    // 512

// ---------------- scratch (static device memory; no runtime allocation) ----
__device__ float g_V [MTOT * DM];                 // X @ Wv^T        (67 MB)
__device__ float g_T [MTOT * DM];                 // X @ Wtheta^T    (67 MB)
__device__ float g_P [SPLITK * BB * DM * DM];     // split-K partials(67 MB)
__device__ float g_KV[BB * DM * DM];              // T^T @ V         (4 MB)
__device__ float g_Pm[BB * 16 * DM];              // colsum partials
__device__ float g_Mv[BB * DM];                   // column means of V

// ============================================================================
// GEMM 1 (NT): C[m,j] = sum_k A[m,k] * W[j,k];  A = X [MTOT,512], W [512,512]
// blockIdx.z selects (Wv -> g_V) or (Wtheta -> g_T)
// ============================================================================
__global__ void __launch_bounds__(256, 2) gemm_nt_kernel(
    const float* __restrict__ X,
    const float* __restrict__ Wv,
    const float* __restrict__ Wt)
{
    __shared__ float As[16][128];
    __shared__ float Bs[16][128];
    const int tid = threadIdx.x;
    const int m0  = blockIdx.x * 128;
    const int n0  = blockIdx.y * 128;
    const float* __restrict__ Bm = (blockIdx.z == 0) ? Wv : Wt;
    float* __restrict__ C        = (blockIdx.z == 0) ? g_V : g_T;

    const int tx = tid & 15;
    const int ty = tid >> 4;

    float acc[8][8];
#pragma unroll
    for (int i = 0; i < 8; i++)
#pragma unroll
        for (int j = 0; j < 8; j++) acc[i][j] = 0.f;

    for (int k0 = 0; k0 < DM; k0 += 16) {
#pragma unroll
        for (int it = 0; it < 2; it++) {
            int idx = tid + it * 256;          // 512 float4 slots
            int row = idx >> 2;                // 0..127
            int kq  = (idx & 3) << 2;          // 0,4,8,12
            float4 va = *(const float4*)(X  + (size_t)(m0 + row) * DM + k0 + kq);
            As[kq + 0][row] = va.x; As[kq + 1][row] = va.y;
            As[kq + 2][row] = va.z; As[kq + 3][row] = va.w;
            float4 vb = *(const float4*)(Bm + (size_t)(n0 + row) * DM + k0 + kq);
            Bs[kq + 0][row] = vb.x; Bs[kq + 1][row] = vb.y;
            Bs[kq + 2][row] = vb.z; Bs[kq + 3][row] = vb.w;
        }
        __syncthreads();
#pragma unroll
        for (int k = 0; k < 16; k++) {
            float a[8], b[8];
            *(float4*)(a)     = *(const float4*)(&As[k][ty * 8]);
            *(float4*)(a + 4) = *(const float4*)(&As[k][ty * 8 + 4]);
            *(float4*)(b)     = *(const float4*)(&Bs[k][tx * 8]);
            *(float4*)(b + 4) = *(const float4*)(&Bs[k][tx * 8 + 4]);
#pragma unroll
            for (int i = 0; i < 8; i++)
#pragma unroll
                for (int j = 0; j < 8; j++)
                    acc[i][j] = fmaf(a[i], b[j], acc[i][j]);
        }
        __syncthreads();
    }

#pragma unroll
    for (int i = 0; i < 8; i++) {
        float* crow = C + (size_t)(m0 + ty * 8 + i) * DM + n0 + tx * 8;
        *(float4*)(crow)     = make_float4(acc[i][0], acc[i][1], acc[i][2], acc[i][3]);
        *(float4*)(crow + 4) = make_float4(acc[i][4], acc[i][5], acc[i][6], acc[i][7]);
    }
}

// ============================================================================
// Column-sum of V, stage 1: g_Pm[b][chunk][j] = sum over 512 rows
// grid (BB, 4, 16), 128 threads
// ============================================================================
__global__ void colsum1_kernel()
{
    const int b  = blockIdx.x;
    const int jt = blockIdx.y;
    const int ch = blockIdx.z;
    const int j  = jt * 128 + threadIdx.x;
    const float* base = g_V + ((size_t)b * NSEQ + (size_t)ch * 512) * DM + j;
    float s0 = 0.f, s1 = 0.f, s2 = 0.f, s3 = 0.f;
    for (int i = 0; i < 512; i += 4) {
        s0 += base[(size_t)(i + 0) * DM];
        s1 += base[(size_t)(i + 1) * DM];
        s2 += base[(size_t)(i + 2) * DM];
        s3 += base[(size_t)(i + 3) * DM];
    }
    g_Pm[(b * 16 + ch) * DM + j] = (s0 + s1) + (s2 + s3);
}

// stage 2: mean. grid (BB, 4), 128 threads
__global__ void colsum2_kernel()
{
    const int b = blockIdx.x;
    const int j = blockIdx.y * 128 + threadIdx.x;
    float s = 0.f;
#pragma unroll
    for (int c = 0; c < 16; c++) s += g_Pm[(b * 16 + c) * DM + j];
    g_Mv[b * DM + j] = s * (1.0f / (float)NSEQ);
}

// ============================================================================
// GEMM 2 (TN, split-K): P[s][b][i][j] = sum_{k in chunk s} T[b,k,i] * V[b,k,j]
// grid (4, 4, BB*SPLITK), 256 threads
// ============================================================================
__global__ void __launch_bounds__(256, 2) gemm_tn_kernel()
{
    __shared__ float As[16][128];
    __shared__ float Bs[16][128];
    const int tid = threadIdx.x;
    const int i0  = blockIdx.x * 128;
    const int j0  = blockIdx.y * 128;
    const int b   = blockIdx.z / SPLITK;
    const int s   = blockIdx.z % SPLITK;
    const float* __restrict__ A  = g_T + ((size_t)b * NSEQ + (size_t)s * KC) * DM;
    const float* __restrict__ Bm = g_V + ((size_t)b * NSEQ + (size_t)s * KC) * DM;

    const int tx = tid & 15;
    const int ty = tid >> 4;

    float acc[8][8];
#pragma unroll
    for (int i = 0; i < 8; i++)
#pragma unroll
        for (int j = 0; j < 8; j++) acc[i][j] = 0.f;

    for (int k0 = 0; k0 < KC; k0 += 16) {
#pragma unroll
        for (int it = 0; it < 2; it++) {
            int idx = tid + it * 256;
            int kr  = idx >> 5;                 // 0..15
            int cq  = (idx & 31) << 2;          // 0..124
            *(float4*)(&As[kr][cq]) = *(const float4*)(A  + (size_t)(k0 + kr) * DM + i0 + cq);
            *(float4*)(&Bs[kr][cq]) = *(const float4*)(Bm + (size_t)(k0 + kr) * DM + j0 + cq);
        }
        __syncthreads();
#pragma unroll
        for (int k = 0; k < 16; k++) {
            float a[8], b2[8];
            *(float4*)(a)      = *(const float4*)(&As[k][ty * 8]);
            *(float4*)(a + 4)  = *(const float4*)(&As[k][ty * 8 + 4]);
            *(float4*)(b2)     = *(const float4*)(&Bs[k][tx * 8]);
            *(float4*)(b2 + 4) = *(const float4*)(&Bs[k][tx * 8 + 4]);
#pragma unroll
            for (int i = 0; i < 8; i++)
#pragma unroll
                for (int j = 0; j < 8; j++)
                    acc[i][j] = fmaf(a[i], b2[j], acc[i][j]);
        }
        __syncthreads();
    }

    float* C = g_P + (size_t)(s * BB + b) * DM * DM;
#pragma unroll
    for (int i = 0; i < 8; i++) {
        float* crow = C + (size_t)(i0 + ty * 8 + i) * DM + j0 + tx * 8;
        *(float4*)(crow)     = make_float4(acc[i][0], acc[i][1], acc[i][2], acc[i][3]);
        *(float4*)(crow + 4) = make_float4(acc[i][4], acc[i][5], acc[i][6], acc[i][7]);
    }
}

// Deterministic split-K reduction: KV = sum_s P[s]
__global__ void reduce_kv_kernel()
{
    const int idx = blockIdx.x * 256 + threadIdx.x;   // over BB*DM*DM
    float s = 0.f;
#pragma unroll
    for (int sp = 0; sp < SPLITK; sp++)
        s += g_P[(size_t)sp * (BB * DM * DM) + idx];
    g_KV[idx] = s;
}

// ============================================================================
// GEMM 3 (NN) + epilogue: out[m,j] = Mv[b][j] + scale * sum_k X[m,k]*KV[b][k,j]
// grid (MTOT/128, 4), 256 threads
// ============================================================================
__global__ void __launch_bounds__(256, 2) gemm_nn_kernel(
    const float* __restrict__ X, float* __restrict__ out)
{
    __shared__ float As[16][128];
    __shared__ float Bs[16][128];
    const int tid = threadIdx.x;
    const int m0  = blockIdx.x * 128;
    const int n0  = blockIdx.y * 128;
    const int b   = m0 / NSEQ;                // 128 | 8192 -> no straddling
    const float* __restrict__ Bm = g_KV + (size_t)b * DM * DM;

    const int tx = tid & 15;
    const int ty = tid >> 4;

    float acc[8][8];
#pragma unroll
    for (int i = 0; i < 8; i++)
#pragma unroll
        for (int j = 0; j < 8; j++) acc[i][j] = 0.f;

    for (int k0 = 0; k0 < DM; k0 += 16) {
#pragma unroll
        for (int it = 0; it < 2; it++) {
            int idx = tid + it * 256;
            // A: row-major, transpose into As[k][m]
            int row = idx >> 2;
            int kq  = (idx & 3) << 2;
            float4 va = *(const float4*)(X + (size_t)(m0 + row) * DM + k0 + kq);
            As[kq + 0][row] = va.x; As[kq + 1][row] = va.y;
            As[kq + 2][row] = va.z; As[kq + 3][row] = va.w;
            // B: row-major [K,N], direct into Bs[k][j]
            int kr = idx >> 5;
            int cq = (idx & 31) << 2;
            *(float4*)(&Bs[kr][cq]) = *(const float4*)(Bm + (size_t)(k0 + kr) * DM + n0 + cq);
        }
        __syncthreads();
#pragma unroll
        for (int k = 0; k < 16; k++) {
            float a[8], b2[8];
            *(float4*)(a)      = *(const float4*)(&As[k][ty * 8]);
            *(float4*)(a + 4)  = *(const float4*)(&As[k][ty * 8 + 4]);
            *(float4*)(b2)     = *(const float4*)(&Bs[k][tx * 8]);
            *(float4*)(b2 + 4) = *(const float4*)(&Bs[k][tx * 8 + 4]);
#pragma unroll
            for (int i = 0; i < 8; i++)
#pragma unroll
                for (int j = 0; j < 8; j++)
                    acc[i][j] = fmaf(a[i], b2[j], acc[i][j]);
        }
        __syncthreads();
    }

    const float scale = 1.0f / (8192.0f * sqrtf(512.0f));   // 1/(n*sqrt(d))
    const int c = n0 + tx * 8;
    float4 mv0 = *(const float4*)(&g_Mv[b * DM + c]);
    float4 mv1 = *(const float4*)(&g_Mv[b * DM + c + 4]);
#pragma unroll
    for (int i = 0; i < 8; i++) {
        float* crow = out + (size_t)(m0 + ty * 8 + i) * DM + c;
        *(float4*)(crow) = make_float4(mv0.x + scale * acc[i][0],
                                       mv0.y + scale * acc[i][1],
                                       mv0.z + scale * acc[i][2],
                                       mv0.w + scale * acc[i][3]);
        *(float4*)(crow + 4) = make_float4(mv1.x + scale * acc[i][4],
                                           mv1.y + scale * acc[i][5],
                                           mv1.z + scale * acc[i][6],
                                           mv1.w + scale * acc[i][7]);
    }
}

// ============================================================================
extern "C" void kernel_launch(void* const* d_in, const int* in_sizes, int n_in,
                              void* d_out, int out_size)
{
    (void)in_sizes; (void)n_in; (void)out_size;
    const float* X  = (const float*)d_in[0];
    const float* Wv = (const float*)d_in[1];
    const float* Wt = (const float*)d_in[2];
    float* out = (float*)d_out;

    // 1) V = X @ Wv^T, T = X @ Wtheta^T
    gemm_nt_kernel<<<dim3(MTOT / 128, DM / 128, 2), 256>>>(X, Wv, Wt);
    // 2) column mean of V
    colsum1_kernel<<<dim3(BB, 4, 16), 128>>>();
    colsum2_kernel<<<dim3(BB, 4), 128>>>();
    // 3) KV[b] = T[b]^T @ V[b]  (split-K, deterministic reduce)
    gemm_tn_kernel<<<dim3(DM / 128, DM / 128, BB * SPLITK), 256>>>();
    reduce_kv_kernel<<<dim3((BB * DM * DM) / 256), 256>>>();
    // 4) out = mean + scale * X @ KV
    gemm_nn_kernel<<<dim3(MTOT / 128, DM / 128), 256>>>(X, out);
}

// round 6
// speedup vs baseline: 2.1624x; 2.1624x over previous
#include <cuda_runtime.h>
#include <math.h>

#define BB     4
#define NSEQ   8192
#define DM     512
#define MTOT   (BB * NSEQ)       // 32768
#define SPLITK 32
#define KC     (NSEQ / SPLITK)   // 256

// ---------------- scratch (static device memory; no runtime allocation) ----
// NOTE: these symbols are referenced ONLY from device code. Passing them as
// host-side kernel args gives the host shadow address (ATS silently reads
// host memory on GB300) — that was the round-5 bug.
__device__ float g_P [SPLITK * BB * DM * DM];   // X^T X split-K partials (134 MB)
__device__ float g_G [BB * DM * DM];            // X^T X                  (4 MB)
__device__ float g_M1[BB * DM * DM];            // Wtheta @ G             (4 MB)
__device__ float g_KV[BB * DM * DM];            // Wtheta @ G @ Wv^T      (4 MB)
__device__ float g_Pm[BB * 16 * DM];            // mean(X) partials
__device__ float g_xm[BB * DM];                 // mean over n of X
__device__ float g_first[BB * DM];              // mean(X) @ Wv^T

// upper-triangle 128x128 tile list for the symmetric 512x512 output
__constant__ int c_ti[10] = {0,0,0,0,1,1,1,2,2,3};
__constant__ int c_tj[10] = {0,1,2,3,1,2,3,2,3,3};

// ============================================================================
// X^T X (TN, split-K, upper-triangle tiles), double-buffered.
// grid (10, BB*SPLITK), 256 threads. P[s][b][i][j] = sum_k X[b,k,i] X[b,k,j]
// ============================================================================
__global__ void __launch_bounds__(256, 2) xtx_kernel(const float* __restrict__ X)
{
    __shared__ float As[2][16][128];
    __shared__ float Bs[2][16][128];
    const int tid = threadIdx.x;
    const int ti  = c_ti[blockIdx.x];
    const int tj  = c_tj[blockIdx.x];
    const int b   = blockIdx.y / SPLITK;
    const int s   = blockIdx.y % SPLITK;
    const float* __restrict__ base = X + ((size_t)b * NSEQ + (size_t)s * KC) * DM;
    const float* __restrict__ Ab = base + ti * 128;
    const float* __restrict__ Bb = base + tj * 128;

    const int kr0 = tid >> 5;            // 0..7
    const int kr1 = kr0 + 8;             // 8..15
    const int cq0 = (tid & 31) << 2;     // 0..124
    const int tx  = tid & 15;
    const int ty  = tid >> 4;

    float acc[8][8];
#pragma unroll
    for (int i = 0; i < 8; i++)
#pragma unroll
        for (int j = 0; j < 8; j++) acc[i][j] = 0.f;

    // prologue: k-tile 0 -> buffer 0
    float4 a0 = *(const float4*)(Ab + (size_t)kr0 * DM + cq0);
    float4 a1 = *(const float4*)(Ab + (size_t)kr1 * DM + cq0);
    float4 b0 = *(const float4*)(Bb + (size_t)kr0 * DM + cq0);
    float4 b1 = *(const float4*)(Bb + (size_t)kr1 * DM + cq0);
    *(float4*)&As[0][kr0][cq0] = a0;
    *(float4*)&As[0][kr1][cq0] = a1;
    *(float4*)&Bs[0][kr0][cq0] = b0;
    *(float4*)&Bs[0][kr1][cq0] = b1;
    __syncthreads();

    const int NK = KC / 16;              // 16
    for (int kt = 0; kt < NK; kt++) {
        const int cur = kt & 1;
        if (kt + 1 < NK) {
            const float* An = Ab + (size_t)(kt + 1) * 16 * DM;
            const float* Bn = Bb + (size_t)(kt + 1) * 16 * DM;
            a0 = *(const float4*)(An + (size_t)kr0 * DM + cq0);
            a1 = *(const float4*)(An + (size_t)kr1 * DM + cq0);
            b0 = *(const float4*)(Bn + (size_t)kr0 * DM + cq0);
            b1 = *(const float4*)(Bn + (size_t)kr1 * DM + cq0);
        }
#pragma unroll
        for (int k = 0; k < 16; k++) {
            float a[8], bb[8];
            *(float4*)(a)      = *(const float4*)&As[cur][k][ty * 8];
            *(float4*)(a + 4)  = *(const float4*)&As[cur][k][ty * 8 + 4];
            *(float4*)(bb)     = *(const float4*)&Bs[cur][k][tx * 8];
            *(float4*)(bb + 4) = *(const float4*)&Bs[cur][k][tx * 8 + 4];
#pragma unroll
            for (int i = 0; i < 8; i++)
#pragma unroll
                for (int j = 0; j < 8; j++)
                    acc[i][j] = fmaf(a[i], bb[j], acc[i][j]);
        }
        if (kt + 1 < NK) {
            const int nxt = cur ^ 1;
            *(float4*)&As[nxt][kr0][cq0] = a0;
            *(float4*)&As[nxt][kr1][cq0] = a1;
            *(float4*)&Bs[nxt][kr0][cq0] = b0;
            *(float4*)&Bs[nxt][kr1][cq0] = b1;
        }
        __syncthreads();
    }

    float* C = g_P + ((size_t)(s * BB + b)) * DM * DM;
#pragma unroll
    for (int i = 0; i < 8; i++) {
        float* crow = C + (size_t)(ti * 128 + ty * 8 + i) * DM + tj * 128 + tx * 8;
        *(float4*)(crow)     = make_float4(acc[i][0], acc[i][1], acc[i][2], acc[i][3]);
        *(float4*)(crow + 4) = make_float4(acc[i][4], acc[i][5], acc[i][6], acc[i][7]);
    }
}

// ============================================================================
// Deterministic split-K reduce + symmetric mirror: G[b] = sum_s P[s][b]
// ============================================================================
__global__ void reduce_g_kernel()
{
    const int idx = blockIdx.x * 256 + threadIdx.x;   // over BB*DM*DM
    const int b = idx >> 18;                          // DM*DM = 2^18
    const int r = idx & (DM * DM - 1);
    const int i = r >> 9;
    const int j = r & 511;
    if (j < i) return;
    float s = 0.f;
#pragma unroll
    for (int sp = 0; sp < SPLITK; sp++)
        s += g_P[((size_t)(sp * BB + b)) * DM * DM + r];
    g_G[(size_t)b * DM * DM + (size_t)i * DM + j] = s;
    g_G[(size_t)b * DM * DM + (size_t)j * DM + i] = s;
}

// ============================================================================
// mean over n of X, stage 1: partial column sums per 512-row chunk
// ============================================================================
__global__ void meanx1_kernel(const float* __restrict__ X)
{
    const int b  = blockIdx.x;
    const int jt = blockIdx.y;
    const int ch = blockIdx.z;
    const int j  = jt * 128 + threadIdx.x;
    const float* base = X + ((size_t)b * NSEQ + (size_t)ch * 512) * DM + j;
    float s0 = 0.f, s1 = 0.f, s2 = 0.f, s3 = 0.f;
    for (int i = 0; i < 512; i += 4) {
        s0 += base[(size_t)(i + 0) * DM];
        s1 += base[(size_t)(i + 1) * DM];
        s2 += base[(size_t)(i + 2) * DM];
        s3 += base[(size_t)(i + 3) * DM];
    }
    g_Pm[(b * 16 + ch) * DM + j] = (s0 + s1) + (s2 + s3);
}

__global__ void meanx2_kernel()
{
    const int b = blockIdx.x;
    const int j = blockIdx.y * 128 + threadIdx.x;
    float s = 0.f;
#pragma unroll
    for (int c = 0; c < 16; c++) s += g_Pm[(b * 16 + c) * DM + j];
    g_xm[b * DM + j] = s * (1.0f / (float)NSEQ);
}

// first[b][j] = sum_k xm[b][k] * Wv[j][k]   — grid (BB, 64), 256 threads
__global__ void first_kernel(const float* __restrict__ Wv)
{
    const int b    = blockIdx.x;
    const int j    = blockIdx.y * 8 + (threadIdx.x >> 5);
    const int lane = threadIdx.x & 31;
    const float* xm = g_xm + b * DM;
    const float* w  = Wv + (size_t)j * DM;
    float s = 0.f;
    for (int k = lane; k < DM; k += 32) s += xm[k] * w[k];
#pragma unroll
    for (int o = 16; o; o >>= 1) s += __shfl_xor_sync(0xFFFFFFFFu, s, o);
    if (lane == 0) g_first[b * DM + j] = s;
}

// ============================================================================
// small batched 512x512x512 GEMM, 64x64 tiles, 128 threads.
// mode 0: M1[b] = W (=Wtheta, NN) @ G[b]      (A = W param,  B = g_G,  C = g_M1)
// mode 1: KV[b] = M1[b] @ W^T (=Wv^T, NT)     (A = g_M1,     B = W,    C = g_KV)
// Scratch globals resolved INSIDE the kernel (round-5 bugfix).
// ============================================================================
__global__ void __launch_bounds__(128) small_gemm_kernel(
    const float* __restrict__ W, int mode)
{
    __shared__ float As[16][68];
    __shared__ float Bs[16][68];
    const int tid = threadIdx.x;
    const int i0  = blockIdx.x * 64;
    const int j0  = blockIdx.y * 64;
    const int b   = blockIdx.z;
    const size_t bo = (size_t)b * DM * DM;
    const float* __restrict__ A = (mode == 0) ? W : (g_M1 + bo);
    const float* __restrict__ B = (mode == 0) ? (g_G + bo) : W;
    float* __restrict__ C       = (mode == 0) ? (g_M1 + bo) : (g_KV + bo);
    const int transB = mode;     // mode 1 is the NT GEMM

    const int tx = tid & 15;     // 16 -> 64 cols (x4)
    const int ty = tid >> 4;     // 8  -> 64 rows (x8)

    const int r0  = tid >> 2;            // 0..31 (transpose-scatter)
    const int r1  = r0 + 32;             // 32..63
    const int kq0 = (tid & 3) << 2;      // 0,4,8,12
    const int kr0 = tid >> 4;            // 0..7 (NN direct)
    const int kr1 = kr0 + 8;
    const int cq0 = (tid & 15) << 2;     // 0..60

    float acc[8][4];
#pragma unroll
    for (int i = 0; i < 8; i++)
#pragma unroll
        for (int j = 0; j < 4; j++) acc[i][j] = 0.f;

    for (int k0 = 0; k0 < DM; k0 += 16) {
        float4 va0 = *(const float4*)(A + (size_t)(i0 + r0) * DM + k0 + kq0);
        float4 va1 = *(const float4*)(A + (size_t)(i0 + r1) * DM + k0 + kq0);
        As[kq0 + 0][r0] = va0.x; As[kq0 + 1][r0] = va0.y;
        As[kq0 + 2][r0] = va0.z; As[kq0 + 3][r0] = va0.w;
        As[kq0 + 0][r1] = va1.x; As[kq0 + 1][r1] = va1.y;
        As[kq0 + 2][r1] = va1.z; As[kq0 + 3][r1] = va1.w;
        if (transB) {
            float4 vb0 = *(const float4*)(B + (size_t)(j0 + r0) * DM + k0 + kq0);
            float4 vb1 = *(const float4*)(B + (size_t)(j0 + r1) * DM + k0 + kq0);
            Bs[kq0 + 0][r0] = vb0.x; Bs[kq0 + 1][r0] = vb0.y;
            Bs[kq0 + 2][r0] = vb0.z; Bs[kq0 + 3][r0] = vb0.w;
            Bs[kq0 + 0][r1] = vb1.x; Bs[kq0 + 1][r1] = vb1.y;
            Bs[kq0 + 2][r1] = vb1.z; Bs[kq0 + 3][r1] = vb1.w;
        } else {
            float4 vb0 = *(const float4*)(B + (size_t)(k0 + kr0) * DM + j0 + cq0);
            float4 vb1 = *(const float4*)(B + (size_t)(k0 + kr1) * DM + j0 + cq0);
            *(float4*)&Bs[kr0][cq0] = vb0;
            *(float4*)&Bs[kr1][cq0] = vb1;
        }
        __syncthreads();
#pragma unroll
        for (int k = 0; k < 16; k++) {
            float a[8], bb[4];
            *(float4*)(a)     = *(const float4*)&As[k][ty * 8];
            *(float4*)(a + 4) = *(const float4*)&As[k][ty * 8 + 4];
            *(float4*)(bb)    = *(const float4*)&Bs[k][tx * 4];
#pragma unroll
            for (int i = 0; i < 8; i++)
#pragma unroll
                for (int j = 0; j < 4; j++)
                    acc[i][j] = fmaf(a[i], bb[j], acc[i][j]);
        }
        __syncthreads();
    }

#pragma unroll
    for (int i = 0; i < 8; i++)
        *(float4*)(C + (size_t)(i0 + ty * 8 + i) * DM + j0 + tx * 4) =
            make_float4(acc[i][0], acc[i][1], acc[i][2], acc[i][3]);
}

// ============================================================================
// final (NN) + epilogue, double-buffered:
// out[m,j] = first[b][j] + scale * sum_k X[m,k] * KV[b][k,j]
// grid (MTOT/128, 4), 256 threads
// ============================================================================
__global__ void __launch_bounds__(256, 2) final_kernel(
    const float* __restrict__ X, float* __restrict__ out)
{
    __shared__ float As[2][16][132];     // padded: kills scatter STS conflicts
    __shared__ float Bs[2][16][128];
    const int tid = threadIdx.x;
    const int m0  = blockIdx.x * 128;
    const int n0  = blockIdx.y * 128;
    const int b   = m0 / NSEQ;           // 128 | 8192 -> no straddling
    const float* __restrict__ Bm = g_KV + (size_t)b * DM * DM;

    const int ar0 = tid >> 2;            // 0..63
    const int ar1 = ar0 + 64;            // 64..127
    const int akq = (tid & 3) << 2;      // 0,4,8,12
    const int kr0 = tid >> 5;            // 0..7
    const int kr1 = kr0 + 8;
    const int cq0 = (tid & 31) << 2;
    const int tx  = tid & 15;
    const int ty  = tid >> 4;

    float acc[8][8];
#pragma unroll
    for (int i = 0; i < 8; i++)
#pragma unroll
        for (int j = 0; j < 8; j++) acc[i][j] = 0.f;

    // prologue
    float4 va0 = *(const float4*)(X + (size_t)(m0 + ar0) * DM + akq);
    float4 va1 = *(const float4*)(X + (size_t)(m0 + ar1) * DM + akq);
    float4 vb0 = *(const float4*)(Bm + (size_t)kr0 * DM + n0 + cq0);
    float4 vb1 = *(const float4*)(Bm + (size_t)kr1 * DM + n0 + cq0);
    As[0][akq + 0][ar0] = va0.x; As[0][akq + 1][ar0] = va0.y;
    As[0][akq + 2][ar0] = va0.z; As[0][akq + 3][ar0] = va0.w;
    As[0][akq + 0][ar1] = va1.x; As[0][akq + 1][ar1] = va1.y;
    As[0][akq + 2][ar1] = va1.z; As[0][akq + 3][ar1] = va1.w;
    *(float4*)&Bs[0][kr0][cq0] = vb0;
    *(float4*)&Bs[0][kr1][cq0] = vb1;
    __syncthreads();

    const int NK = DM / 16;              // 32
    for (int kt = 0; kt < NK; kt++) {
        const int cur = kt & 1;
        if (kt + 1 < NK) {
            const int k0 = (kt + 1) * 16;
            va0 = *(const float4*)(X + (size_t)(m0 + ar0) * DM + k0 + akq);
            va1 = *(const float4*)(X + (size_t)(m0 + ar1) * DM + k0 + akq);
            vb0 = *(const float4*)(Bm + (size_t)(k0 + kr0) * DM + n0 + cq0);
            vb1 = *(const float4*)(Bm + (size_t)(k0 + kr1) * DM + n0 + cq0);
        }
#pragma unroll
        for (int k = 0; k < 16; k++) {
            float a[8], bb[8];
            *(float4*)(a)      = *(const float4*)&As[cur][k][ty * 8];
            *(float4*)(a + 4)  = *(const float4*)&As[cur][k][ty * 8 + 4];
            *(float4*)(bb)     = *(const float4*)&Bs[cur][k][tx * 8];
            *(float4*)(bb + 4) = *(const float4*)&Bs[cur][k][tx * 8 + 4];
#pragma unroll
            for (int i = 0; i < 8; i++)
#pragma unroll
                for (int j = 0; j < 8; j++)
                    acc[i][j] = fmaf(a[i], bb[j], acc[i][j]);
        }
        if (kt + 1 < NK) {
            const int nxt = cur ^ 1;
            As[nxt][akq + 0][ar0] = va0.x; As[nxt][akq + 1][ar0] = va0.y;
            As[nxt][akq + 2][ar0] = va0.z; As[nxt][akq + 3][ar0] = va0.w;
            As[nxt][akq + 0][ar1] = va1.x; As[nxt][akq + 1][ar1] = va1.y;
            As[nxt][akq + 2][ar1] = va1.z; As[nxt][akq + 3][ar1] = va1.w;
            *(float4*)&Bs[nxt][kr0][cq0] = vb0;
            *(float4*)&Bs[nxt][kr1][cq0] = vb1;
        }
        __syncthreads();
    }

    const float scale = 1.0f / (8192.0f * sqrtf(512.0f));   // 1/(n*sqrt(d))
    const int c = n0 + tx * 8;
    float4 mv0 = *(const float4*)(&g_first[b * DM + c]);
    float4 mv1 = *(const float4*)(&g_first[b * DM + c + 4]);
#pragma unroll
    for (int i = 0; i < 8; i++) {
        float* crow = out + (size_t)(m0 + ty * 8 + i) * DM + c;
        *(float4*)(crow) = make_float4(mv0.x + scale * acc[i][0],
                                       mv0.y + scale * acc[i][1],
                                       mv0.z + scale * acc[i][2],
                                       mv0.w + scale * acc[i][3]);
        *(float4*)(crow + 4) = make_float4(mv1.x + scale * acc[i][4],
                                           mv1.y + scale * acc[i][5],
                                           mv1.z + scale * acc[i][6],
                                           mv1.w + scale * acc[i][7]);
    }
}

// ============================================================================
extern "C" void kernel_launch(void* const* d_in, const int* in_sizes, int n_in,
                              void* d_out, int out_size)
{
    (void)in_sizes; (void)n_in; (void)out_size;
    const float* X  = (const float*)d_in[0];
    const float* Wv = (const float*)d_in[1];
    const float* Wt = (const float*)d_in[2];
    float* out = (float*)d_out;

    // 1) G[b] = X[b]^T X[b]  (split-K over n, upper-triangle tiles only)
    xtx_kernel<<<dim3(10, BB * SPLITK), 256>>>(X);
    // 2) mean over n of X, then first = mean(X) @ Wv^T
    meanx1_kernel<<<dim3(BB, 4, 16), 128>>>(X);
    meanx2_kernel<<<dim3(BB, 4), 128>>>();
    first_kernel<<<dim3(BB, 64), 256>>>(Wv);
    // 3) reduce + mirror G
    reduce_g_kernel<<<dim3((BB * DM * DM) / 256), 256>>>();
    // 4) M1[b] = Wtheta @ G[b]  (mode 0, NN);  KV[b] = M1[b] @ Wv^T  (mode 1, NT)
    small_gemm_kernel<<<dim3(8, 8, BB), 128>>>(Wt, 0);
    small_gemm_kernel<<<dim3(8, 8, BB), 128>>>(Wv, 1);
    // 5) out = first + scale * X @ KV
    final_kernel<<<dim3(MTOT / 128, DM / 128), 256>>>(X, out);
}